// round 1
// baseline (speedup 1.0000x reference)
#include <cuda_runtime.h>
#include <math.h>

#define HW 4096
#define BATCH 2

// Scratch (device globals — no allocation allowed)
__device__ float g_qkv[BATCH * 288 * HW];  // rows: 0-95 Q, 96-191 K, 192-287 V  (channel = head*24+d)
__device__ float g_att[BATCH * 288 * HW];  // channel = head*72 + range*24 + d

// ---------------------------------------------------------------------------
// SGEMM: C[b][m][pix] = bias[m] + sum_k W[m][k] * X[b][k][pix]
// M = 96 fixed. BN=64, BK=8, TM=6, TN=4, 256 threads.
// ---------------------------------------------------------------------------
template <int K>
__global__ __launch_bounds__(256) void sgemm96(
    const float* __restrict__ Wm, const float* __restrict__ bias,
    const float* __restrict__ X, long xstride,
    float* __restrict__ C, long cstride)
{
    constexpr int BN = 64, BK = 8, TM = 6, TN = 4;
    __shared__ float Ws[BK][96];
    __shared__ float Xs[BK][BN];

    const float* Xb = X + (long)blockIdx.y * xstride;
    float* Cb = C + (long)blockIdx.y * cstride;
    const int n0 = blockIdx.x * BN;
    const int tid = threadIdx.x;
    const int tx = tid & 15;   // n dim
    const int ty = tid >> 4;   // m dim

    float acc[TM][TN] = {};

    for (int k0 = 0; k0 < K; k0 += BK) {
        // load W tile (96 x 8), transposed into Ws[kk][m]
        #pragma unroll
        for (int i = 0; i < 3; i++) {
            int idx = tid + i * 256;        // 0..767
            int m = idx >> 3, kk = idx & 7;
            Ws[kk][m] = Wm[m * K + k0 + kk];
        }
        // load X tile (8 x 64)
        #pragma unroll
        for (int i = 0; i < 2; i++) {
            int idx = tid + i * 256;        // 0..511
            int kk = idx >> 6, n = idx & 63;
            Xs[kk][n] = Xb[(long)(k0 + kk) * HW + n0 + n];
        }
        __syncthreads();

        #pragma unroll
        for (int kk = 0; kk < BK; kk++) {
            float rm[TM], rn[TN];
            #pragma unroll
            for (int i = 0; i < TM; i++) rm[i] = Ws[kk][ty * TM + i];
            #pragma unroll
            for (int j = 0; j < TN; j++) rn[j] = Xs[kk][tx * TN + j];
            #pragma unroll
            for (int i = 0; i < TM; i++)
                #pragma unroll
                for (int j = 0; j < TN; j++)
                    acc[i][j] += rm[i] * rn[j];
        }
        __syncthreads();
    }

    #pragma unroll
    for (int i = 0; i < TM; i++) {
        int m = ty * TM + i;
        float bv = bias[m];
        float4 o;
        o.x = acc[i][0] + bv;
        o.y = acc[i][1] + bv;
        o.z = acc[i][2] + bv;
        o.w = acc[i][3] + bv;
        *reinterpret_cast<float4*>(&Cb[(long)m * HW + n0 + tx * TN]) = o;
    }
}

// ---------------------------------------------------------------------------
// Attention: one (batch, head, 16x16 tile) per block. 256 threads = 1 px each.
// K/V halo 26x26 x 24 floats in SMEM, pixel stride padded to 28 floats
// (28*4=112B: LDS.128 phases hit all 32 banks -> conflict-free).
// Nested-window trick: acc7 (7x7 core), acc9 (9-ring), acc11 (11-ring).
// Zero halo => OOB score 0 => exp=1 participates in softmax (matches ref pad).
// ---------------------------------------------------------------------------
#define PSTR 28
#define HALO 26
#define ATTN_SMEM (2 * 676 * PSTR * 4)

__global__ __launch_bounds__(256) void attn_kernel()
{
    extern __shared__ float sh[];
    float* Ksh = sh;
    float* Vsh = sh + 676 * PSTR;

    const int tile = blockIdx.x;   // 0..15
    const int head = blockIdx.y;   // 0..3
    const int b    = blockIdx.z;   // 0..1
    const int th = (tile >> 2) << 4;
    const int tw = (tile & 3) << 4;
    const int h0 = th - 5, w0 = tw - 5;

    const float* base = g_qkv + (long)b * 288 * HW;
    const float* Kg = base + (96 + head * 24) * HW;
    const float* Vg = base + (192 + head * 24) * HW;

    const int tid = threadIdx.x;

    // cooperative halo load (zero-fill OOB)
    for (int idx = tid; idx < 676 * 24; idx += 256) {
        int d = idx / 676;
        int p = idx - d * 676;
        int py = p / HALO, px = p - py * HALO;
        int gy = h0 + py, gx = w0 + px;
        float kv = 0.f, vv = 0.f;
        if ((unsigned)gy < 64u && (unsigned)gx < 64u) {
            int g = d * HW + gy * 64 + gx;
            kv = Kg[g];
            vv = Vg[g];
        }
        Ksh[p * PSTR + d] = kv;
        Vsh[p * PSTR + d] = vv;
    }
    __syncthreads();

    const int ly = tid >> 4, lx = tid & 15;

    // Q with 1/sqrt(24) folded in
    const float* Qg = g_qkv + ((long)b * 288 + head * 24) * HW + (th + ly) * 64 + (tw + lx);
    float q[24];
    #pragma unroll
    for (int d = 0; d < 24; d++) q[d] = Qg[(long)d * HW] * 0.2041241452319315f;

    float acc7[24] = {}, acc9[24] = {}, acc11[24] = {};
    float l7 = 0.f, l9 = 0.f, l11 = 0.f;
    const int cbase = (ly + 5) * HALO + (lx + 5);

#define BODY(POFF, ACC, L) { \
    const float* kp = Ksh + (size_t)(cbase + (POFF)) * PSTR; \
    const float* vp = Vsh + (size_t)(cbase + (POFF)) * PSTR; \
    float s0 = 0.f, s1 = 0.f, s2 = 0.f, s3 = 0.f; \
    _Pragma("unroll") \
    for (int d = 0; d < 6; d++) { \
        s0 += q[d]      * kp[d]; \
        s1 += q[d + 6]  * kp[d + 6]; \
        s2 += q[d + 12] * kp[d + 12]; \
        s3 += q[d + 18] * kp[d + 18]; \
    } \
    float e = __expf((s0 + s1) + (s2 + s3)); \
    L += e; \
    _Pragma("unroll") \
    for (int d = 0; d < 24; d++) ACC[d] += e * vp[d]; \
}

    // 7x7 core
    #pragma unroll 1
    for (int dy = -3; dy <= 3; dy++) {
        #pragma unroll 1
        for (int dx = -3; dx <= 3; dx++) { BODY(dy * HALO + dx, acc7, l7) }
    }
    // 9x9 ring (max(|dy|,|dx|) == 4): 32 positions
    #pragma unroll 1
    for (int dx = -4; dx <= 4; dx++) { BODY(-4 * HALO + dx, acc9, l9) BODY(4 * HALO + dx, acc9, l9) }
    #pragma unroll 1
    for (int dy = -3; dy <= 3; dy++) { BODY(dy * HALO - 4, acc9, l9) BODY(dy * HALO + 4, acc9, l9) }
    // 11x11 ring (max == 5): 40 positions
    #pragma unroll 1
    for (int dx = -5; dx <= 5; dx++) { BODY(-5 * HALO + dx, acc11, l11) BODY(5 * HALO + dx, acc11, l11) }
    #pragma unroll 1
    for (int dy = -4; dy <= 4; dy++) { BODY(dy * HALO - 5, acc11, l11) BODY(dy * HALO + 5, acc11, l11) }

#undef BODY

    const float r7  = __fdividef(1.f, l7);
    const float t9  = l7 + l9;
    const float r9  = __fdividef(1.f, t9);
    const float r11 = __fdividef(1.f, t9 + l11);

    float* A = g_att + ((long)b * 288 + head * 72) * HW + (th + ly) * 64 + (tw + lx);
    #pragma unroll
    for (int d = 0; d < 24; d++) {
        float a7  = acc7[d];
        float a9  = a7 + acc9[d];
        float a11 = a9 + acc11[d];
        A[(long)d * HW]        = a7  * r7;
        A[(long)(24 + d) * HW] = a9  * r9;
        A[(long)(48 + d) * HW] = a11 * r11;
    }
}

// ---------------------------------------------------------------------------
extern "C" void kernel_launch(void* const* d_in, const int* in_sizes, int n_in,
                              void* d_out, int out_size)
{
    const float* x  = (const float*)d_in[0];
    const float* wq = (const float*)d_in[1];
    const float* bq = (const float*)d_in[2];
    const float* wk = (const float*)d_in[3];
    const float* bk = (const float*)d_in[4];
    const float* wv = (const float*)d_in[5];
    const float* bv = (const float*)d_in[6];
    const float* wo = (const float*)d_in[7];
    const float* bo = (const float*)d_in[8];
    float* out = (float*)d_out;

    float* qkv = nullptr;
    float* att = nullptr;
    cudaGetSymbolAddress((void**)&qkv, g_qkv);
    cudaGetSymbolAddress((void**)&att, g_att);

    cudaFuncSetAttribute(attn_kernel, cudaFuncAttributeMaxDynamicSharedMemorySize, ATTN_SMEM);

    dim3 gg(64, BATCH);
    // QKV projections
    sgemm96<96><<<gg, 256>>>(wq, bq, x, 96L * HW, qkv,             288L * HW);
    sgemm96<96><<<gg, 256>>>(wk, bk, x, 96L * HW, qkv + 96L * HW,  288L * HW);
    sgemm96<96><<<gg, 256>>>(wv, bv, x, 96L * HW, qkv + 192L * HW, 288L * HW);
    // Multi-range local attention
    attn_kernel<<<dim3(16, 4, BATCH), 256, ATTN_SMEM>>>();
    // Output projection
    sgemm96<288><<<gg, 256>>>(wo, bo, att, 288L * HW, out, 96L * HW);
}

// round 3
// speedup vs baseline: 1.0719x; 1.0719x over previous
#include <cuda_runtime.h>
#include <math.h>

#define HW 4096
#define BATCH 2

typedef unsigned long long ull;

// Scratch (device globals — no allocation allowed)
__device__ float g_qkv[BATCH * 288 * HW];  // rows: 0-95 Q, 96-191 K, 192-287 V
__device__ float g_att[BATCH * 288 * HW];  // channel = head*72 + range*24 + d

// ---------------------------------------------------------------------------
// f32x2 helpers
// ---------------------------------------------------------------------------
__device__ __forceinline__ ull pk2(float a) {
    ull r;
    asm("mov.b64 %0, {%1,%1};" : "=l"(r) : "f"(a));
    return r;
}
__device__ __forceinline__ ull ffma2(ull a, ull b, ull c) {
    ull d;
    asm("fma.rn.f32x2 %0, %1, %2, %3;" : "=l"(d) : "l"(a), "l"(b), "l"(c));
    return d;
}
__device__ __forceinline__ void upk(ull v, float& lo, float& hi) {
    asm("mov.b64 {%0,%1}, %2;" : "=f"(lo), "=f"(hi) : "l"(v));
}

// ---------------------------------------------------------------------------
// SGEMM with packed f32x2 FMA: C[z][b][m][pix] = bias[m] + sum_k W[m][k]*X[b][k][pix]
// M=96 fixed, BN=128, BK=16, TM=8, TN=8, 192 threads (12 x 16).
// blockIdx.z selects one of up to 3 (W, bias, C) triples (fused QKV).
// gridDim.x MUST be HW/128 = 32.
// ---------------------------------------------------------------------------
template <int K>
__global__ __launch_bounds__(192) void gemm_f32x2(
    const float* __restrict__ X, long xstride, long cstride,
    const float* w0, const float* w1, const float* w2,
    const float* b0, const float* b1, const float* b2,
    float* c0, float* c1, float* c2)
{
    const int z = blockIdx.z;
    const float* __restrict__ W    = (z == 0) ? w0 : ((z == 1) ? w1 : w2);
    const float* __restrict__ bias = (z == 0) ? b0 : ((z == 1) ? b1 : b2);
    float* __restrict__ C = ((z == 0) ? c0 : ((z == 1) ? c1 : c2)) + (long)blockIdx.y * cstride;
    const float* __restrict__ Xb = X + (long)blockIdx.y * xstride;

    __shared__ float Ws[16][96];
    __shared__ float Xs[16][128];

    const int tid = threadIdx.x;
    const int tx = tid & 15;    // n (TN=8)
    const int ty = tid >> 4;    // m 0..11 (TM=8)
    const int n0 = blockIdx.x * 128;

    ull acc[8][4] = {};

    for (int k0 = 0; k0 < K; k0 += 16) {
        // W tile 96x16 -> Ws[kk][m] (transposed)
        #pragma unroll
        for (int i = 0; i < 2; i++) {
            int idx = tid + i * 192;            // 0..383
            int m = idx >> 2, kq = (idx & 3) * 4;
            float4 w = *(const float4*)&W[(long)m * K + k0 + kq];
            Ws[kq + 0][m] = w.x;
            Ws[kq + 1][m] = w.y;
            Ws[kq + 2][m] = w.z;
            Ws[kq + 3][m] = w.w;
        }
        // X tile 16x128
        #pragma unroll
        for (int i = 0; i < 3; i++) {
            int idx = tid + i * 192;
            if (idx < 512) {
                int r = idx >> 5, c = (idx & 31) * 4;
                *(float4*)&Xs[r][c] = *(const float4*)&Xb[(long)(k0 + r) * HW + n0 + c];
            }
        }
        __syncthreads();

        #pragma unroll
        for (int kk = 0; kk < 16; kk++) {
            float4 a0 = *(float4*)&Ws[kk][ty * 8];
            float4 a1 = *(float4*)&Ws[kk][ty * 8 + 4];
            double2 x0 = *(double2*)&Xs[kk][tx * 8];
            double2 x1 = *(double2*)&Xs[kk][tx * 8 + 4];
            ull bq[4];
            bq[0] = __double_as_longlong(x0.x);
            bq[1] = __double_as_longlong(x0.y);
            bq[2] = __double_as_longlong(x1.x);
            bq[3] = __double_as_longlong(x1.y);
            ull ad[8] = {pk2(a0.x), pk2(a0.y), pk2(a0.z), pk2(a0.w),
                         pk2(a1.x), pk2(a1.y), pk2(a1.z), pk2(a1.w)};
            #pragma unroll
            for (int i = 0; i < 8; i++)
                #pragma unroll
                for (int j = 0; j < 4; j++)
                    acc[i][j] = ffma2(ad[i], bq[j], acc[i][j]);
        }
        __syncthreads();
    }

    #pragma unroll
    for (int i = 0; i < 8; i++) {
        int m = ty * 8 + i;
        float bv = bias[m];
        float4 o0, o1;
        upk(acc[i][0], o0.x, o0.y);
        upk(acc[i][1], o0.z, o0.w);
        upk(acc[i][2], o1.x, o1.y);
        upk(acc[i][3], o1.z, o1.w);
        o0.x += bv; o0.y += bv; o0.z += bv; o0.w += bv;
        o1.x += bv; o1.y += bv; o1.z += bv; o1.w += bv;
        float* cp = &C[(long)m * HW + n0 + tx * 8];
        *(float4*)cp = o0;
        *(float4*)(cp + 4) = o1;
    }
}

// ---------------------------------------------------------------------------
// Attention: 8x16 pixel tile per CTA, 256 threads = 2 threads per pixel.
// Role A (tid<128): dy <= 0 half of each window; Role B: dy > 0 half.
// Partial (acc7/9/11, l7/9/11) combined through SMEM at the end.
// Halo 18x26 x 24 fp32 for K and V, pixel stride 28 floats (conflict-free LDS.128).
// 105 KB smem -> 2 CTAs/SM; grid 256 CTAs.
// ---------------------------------------------------------------------------
#define PSTR 28
#define HROWS 18
#define HCOLS 26
#define HPX (HROWS * HCOLS)            // 468
#define ATTN_SMEM (2 * HPX * PSTR * 4) // 104832 B

__global__ __launch_bounds__(256, 2) void attn_kernel()
{
    extern __shared__ float sh[];
    float* Ksh = sh;
    float* Vsh = sh + HPX * PSTR;

    const int tr = blockIdx.x >> 2;  // 0..7
    const int tc = blockIdx.x & 3;   // 0..3
    const int head = blockIdx.y;
    const int b = blockIdx.z;
    const int th = tr * 8, tw = tc * 16;
    const int h0 = th - 5, w0 = tw - 5;

    const float* base = g_qkv + (long)b * 288 * HW;
    const float* Kg = base + (96 + head * 24) * HW;
    const float* Vg = base + (192 + head * 24) * HW;

    const int tid = threadIdx.x;

    // cooperative halo load (zero-fill OOB)
    for (int idx = tid; idx < HPX * 24; idx += 256) {
        int d = idx / HPX;
        int p = idx - d * HPX;
        int py = p / HCOLS, px = p - py * HCOLS;
        int gy = h0 + py, gx = w0 + px;
        float kv = 0.f, vv = 0.f;
        if ((unsigned)gy < 64u && (unsigned)gx < 64u) {
            int g = d * HW + gy * 64 + gx;
            kv = Kg[g];
            vv = Vg[g];
        }
        Ksh[p * PSTR + d] = kv;
        Vsh[p * PSTR + d] = vv;
    }
    __syncthreads();

    const int role = tid >> 7;        // 0: dy<=0, 1: dy>0
    const int p = tid & 127;
    const int ly = p >> 4, lx = p & 15;

    // Q with 1/sqrt(24) folded in
    const float* Qg = g_qkv + ((long)b * 288 + head * 24) * HW + (th + ly) * 64 + (tw + lx);
    float q[24];
    #pragma unroll
    for (int d = 0; d < 24; d++) q[d] = Qg[(long)d * HW] * 0.2041241452319315f;

    float acc7[24] = {}, acc9[24] = {}, acc11[24] = {};
    float l7 = 0.f, l9 = 0.f, l11 = 0.f;
    const int cbase = (ly + 5) * HCOLS + (lx + 5);

#define BODY(POFF, ACC, L) { \
    const float* kp = Ksh + (size_t)(cbase + (POFF)) * PSTR; \
    const float* vp = Vsh + (size_t)(cbase + (POFF)) * PSTR; \
    float s0 = 0.f, s1 = 0.f, s2 = 0.f, s3 = 0.f; \
    _Pragma("unroll") \
    for (int d = 0; d < 6; d++) { \
        s0 += q[d]      * kp[d]; \
        s1 += q[d + 6]  * kp[d + 6]; \
        s2 += q[d + 12] * kp[d + 12]; \
        s3 += q[d + 18] * kp[d + 18]; \
    } \
    float e = __expf((s0 + s1) + (s2 + s3)); \
    L += e; \
    _Pragma("unroll") \
    for (int d = 0; d < 24; d++) ACC[d] += e * vp[d]; \
}

    if (role == 0) {
        // ---- dy <= 0 half ----
        #pragma unroll 1
        for (int dy = -3; dy <= 0; dy++)
            #pragma unroll 1
            for (int dx = -3; dx <= 3; dx++) { BODY(dy * HCOLS + dx, acc7, l7) }
        #pragma unroll 1
        for (int dx = -4; dx <= 4; dx++) { BODY(-4 * HCOLS + dx, acc9, l9) }
        #pragma unroll 1
        for (int dy = -3; dy <= 0; dy++) { BODY(dy * HCOLS - 4, acc9, l9) BODY(dy * HCOLS + 4, acc9, l9) }
        #pragma unroll 1
        for (int dx = -5; dx <= 5; dx++) { BODY(-5 * HCOLS + dx, acc11, l11) }
        #pragma unroll 1
        for (int dy = -4; dy <= 0; dy++) { BODY(dy * HCOLS - 5, acc11, l11) BODY(dy * HCOLS + 5, acc11, l11) }
    } else {
        // ---- dy > 0 half ----
        #pragma unroll 1
        for (int dy = 1; dy <= 3; dy++)
            #pragma unroll 1
            for (int dx = -3; dx <= 3; dx++) { BODY(dy * HCOLS + dx, acc7, l7) }
        #pragma unroll 1
        for (int dx = -4; dx <= 4; dx++) { BODY(4 * HCOLS + dx, acc9, l9) }
        #pragma unroll 1
        for (int dy = 1; dy <= 3; dy++) { BODY(dy * HCOLS - 4, acc9, l9) BODY(dy * HCOLS + 4, acc9, l9) }
        #pragma unroll 1
        for (int dx = -5; dx <= 5; dx++) { BODY(5 * HCOLS + dx, acc11, l11) }
        #pragma unroll 1
        for (int dy = 1; dy <= 4; dy++) { BODY(dy * HCOLS - 5, acc11, l11) BODY(dy * HCOLS + 5, acc11, l11) }
    }
#undef BODY

    // ---- combine partials: role B -> smem (aliases Ksh, safe after sync) ----
    __syncthreads();
    float* red = sh;   // 128 px * 77 floats = 39.4 KB (< K region)
    if (role == 1) {
        float* r = red + p * 77;
        #pragma unroll
        for (int d = 0; d < 24; d++) {
            r[d]      = acc7[d];
            r[24 + d] = acc9[d];
            r[48 + d] = acc11[d];
        }
        r[72] = l7; r[73] = l9; r[74] = l11;
    }
    __syncthreads();

    if (role == 0) {
        const float* r = red + p * 77;
        #pragma unroll
        for (int d = 0; d < 24; d++) {
            acc7[d]  += r[d];
            acc9[d]  += r[24 + d];
            acc11[d] += r[48 + d];
        }
        l7 += r[72]; l9 += r[73]; l11 += r[74];

        const float r7  = __fdividef(1.f, l7);
        const float t9  = l7 + l9;
        const float r9  = __fdividef(1.f, t9);
        const float r11 = __fdividef(1.f, t9 + l11);

        float* A = g_att + ((long)b * 288 + head * 72) * HW + (th + ly) * 64 + (tw + lx);
        #pragma unroll
        for (int d = 0; d < 24; d++) {
            float a7  = acc7[d];
            float a9  = a7 + acc9[d];
            float a11 = a9 + acc11[d];
            A[(long)d * HW]        = a7  * r7;
            A[(long)(24 + d) * HW] = a9  * r9;
            A[(long)(48 + d) * HW] = a11 * r11;
        }
    }
}

// ---------------------------------------------------------------------------
extern "C" void kernel_launch(void* const* d_in, const int* in_sizes, int n_in,
                              void* d_out, int out_size)
{
    const float* x  = (const float*)d_in[0];
    const float* wq = (const float*)d_in[1];
    const float* bq = (const float*)d_in[2];
    const float* wk = (const float*)d_in[3];
    const float* bk = (const float*)d_in[4];
    const float* wv = (const float*)d_in[5];
    const float* bv = (const float*)d_in[6];
    const float* wo = (const float*)d_in[7];
    const float* bo = (const float*)d_in[8];
    float* out = (float*)d_out;

    float* qkv = nullptr;
    float* att = nullptr;
    cudaGetSymbolAddress((void**)&qkv, g_qkv);
    cudaGetSymbolAddress((void**)&att, g_att);

    cudaFuncSetAttribute(attn_kernel, cudaFuncAttributeMaxDynamicSharedMemorySize, ATTN_SMEM);

    // Fused QKV projection: grid (HW/128, BATCH, 3) = (32, 2, 3) -> 192 CTAs
    gemm_f32x2<96><<<dim3(32, BATCH, 3), 192>>>(
        x, 96L * HW, 288L * HW,
        wq, wk, wv, bq, bk, bv,
        qkv, qkv + 96L * HW, qkv + 192L * HW);

    // Multi-range local attention (256 CTAs, 2 per SM)
    attn_kernel<<<dim3(32, 4, BATCH), 256, ATTN_SMEM>>>();

    // Output projection: grid (32, 2, 1)
    gemm_f32x2<288><<<dim3(32, BATCH, 1), 192>>>(
        att, 288L * HW, 96L * HW,
        wo, wo, wo, bo, bo, bo,
        out, out, out);
}

// round 5
// speedup vs baseline: 1.1299x; 1.0541x over previous
#include <cuda_runtime.h>
#include <math.h>

#define HW 4096
#define BATCH 2

typedef unsigned long long ull;

// Scratch (device globals — no allocation allowed)
__device__ float g_qkv[BATCH * 288 * HW];  // QKV; later reused as out-proj partial slabs
__device__ float g_att[BATCH * 288 * HW];  // channel = head*72 + range*24 + d

// ---------------------------------------------------------------------------
// f32x2 helpers
// ---------------------------------------------------------------------------
__device__ __forceinline__ ull pk2(float a) {
    ull r; asm("mov.b64 %0, {%1,%1};" : "=l"(r) : "f"(a)); return r;
}
__device__ __forceinline__ ull pkpair(float lo, float hi) {
    ull r; asm("mov.b64 %0, {%1,%2};" : "=l"(r) : "f"(lo), "f"(hi)); return r;
}
__device__ __forceinline__ ull ffma2(ull a, ull b, ull c) {
    ull d; asm("fma.rn.f32x2 %0, %1, %2, %3;" : "=l"(d) : "l"(a), "l"(b), "l"(c)); return d;
}
__device__ __forceinline__ ull add2(ull a, ull b) {
    ull d; asm("add.rn.f32x2 %0, %1, %2;" : "=l"(d) : "l"(a), "l"(b)); return d;
}
__device__ __forceinline__ void upk(ull v, float& lo, float& hi) {
    asm("mov.b64 {%0,%1}, %2;" : "=f"(lo), "=f"(hi) : "l"(v));
}

// ---------------------------------------------------------------------------
// GEMM (f32x2): C[m][pix] = [bias[m] +] sum_{k in chunk} W[m][k] * X[k][pix]
// BM=96, BN=64, BK=16, 128 threads, TM=6, TN=8.
// PARTIAL: z selects K-chunk (kbeg = z*KCHUNK), raw store (no bias).
// !PARTIAL: z selects (W,bias,C) triple (fused QKV), bias added.
// ---------------------------------------------------------------------------
#define WSTR 102   // Ws row stride (conflict-free transposed stores)

template <int KTOT, int KCHUNK, bool PARTIAL>
__global__ __launch_bounds__(128) void gemm_k(
    const float* __restrict__ X, long xstride, long cstride,
    const float* w0, const float* w1, const float* w2,
    const float* b0, const float* b1, const float* b2,
    float* c0, float* c1, float* c2)
{
    const int z = blockIdx.z;
    const float* __restrict__ W;
    const float* __restrict__ bias;
    float* __restrict__ C;
    int kbeg;
    if (PARTIAL) {
        W = w0; bias = b0;
        C = (z == 0) ? c0 : c1;
        kbeg = z * KCHUNK;
    } else {
        W    = (z == 0) ? w0 : ((z == 1) ? w1 : w2);
        bias = (z == 0) ? b0 : ((z == 1) ? b1 : b2);
        C    = (z == 0) ? c0 : ((z == 1) ? c1 : c2);
        kbeg = 0;
    }
    C += (long)blockIdx.y * cstride;
    const float* __restrict__ Xb = X + (long)blockIdx.y * xstride;

    __shared__ float Ws[16][WSTR];
    __shared__ float Xs[16][64];

    const int tid = threadIdx.x;
    const int tx = tid & 7;      // n: 8 cols
    const int ty = tid >> 3;     // m: 0..15, 6 rows each
    const int n0 = blockIdx.x * 64;

    ull acc[6][4] = {};

    for (int k0 = kbeg; k0 < kbeg + KCHUNK; k0 += 16) {
        // W tile 96x16 (transposed into Ws[kk][m]); 384 float4 loads / 128 thr
        #pragma unroll
        for (int i = 0; i < 3; i++) {
            int idx = tid + i * 128;
            int m = idx >> 2, kq = (idx & 3) * 4;
            float4 w = *(const float4*)&W[(long)m * KTOT + k0 + kq];
            Ws[kq + 0][m] = w.x;
            Ws[kq + 1][m] = w.y;
            Ws[kq + 2][m] = w.z;
            Ws[kq + 3][m] = w.w;
        }
        // X tile 16x64; 256 float4 / 128 thr
        #pragma unroll
        for (int i = 0; i < 2; i++) {
            int idx = tid + i * 128;
            int r = idx >> 4, c = (idx & 15) * 4;
            *(float4*)&Xs[r][c] = *(const float4*)&Xb[(long)(k0 + r) * HW + n0 + c];
        }
        __syncthreads();

        #pragma unroll
        for (int kk = 0; kk < 16; kk++) {
            float2 a01 = *(float2*)&Ws[kk][ty * 6];
            float2 a23 = *(float2*)&Ws[kk][ty * 6 + 2];
            float2 a45 = *(float2*)&Ws[kk][ty * 6 + 4];
            ull ad[6] = {pk2(a01.x), pk2(a01.y), pk2(a23.x),
                         pk2(a23.y), pk2(a45.x), pk2(a45.y)};
            ulonglong2 x0 = *(ulonglong2*)&Xs[kk][tx * 8];
            ulonglong2 x1 = *(ulonglong2*)&Xs[kk][tx * 8 + 4];
            ull bq[4] = {x0.x, x0.y, x1.x, x1.y};
            #pragma unroll
            for (int i = 0; i < 6; i++)
                #pragma unroll
                for (int j = 0; j < 4; j++)
                    acc[i][j] = ffma2(ad[i], bq[j], acc[i][j]);
        }
        __syncthreads();
    }

    #pragma unroll
    for (int i = 0; i < 6; i++) {
        int m = ty * 6 + i;
        float bv = PARTIAL ? 0.f : bias[m];
        float4 o0, o1;
        upk(acc[i][0], o0.x, o0.y);
        upk(acc[i][1], o0.z, o0.w);
        upk(acc[i][2], o1.x, o1.y);
        upk(acc[i][3], o1.z, o1.w);
        o0.x += bv; o0.y += bv; o0.z += bv; o0.w += bv;
        o1.x += bv; o1.y += bv; o1.z += bv; o1.w += bv;
        float* cp = &C[(long)m * HW + n0 + tx * 8];
        *(float4*)cp = o0;
        *(float4*)(cp + 4) = o1;
    }
}

// out = p0 + p1 + bias[m];  layouts all [b][96][4096]
__global__ __launch_bounds__(256) void finish_out(
    const float* __restrict__ p0, const float* __restrict__ p1,
    const float* __restrict__ bo, float* __restrict__ out)
{
    int idx = blockIdx.x * 256 + threadIdx.x;       // float4 index, < 196608
    int m = (idx >> 10) % 96;
    float bv = bo[m];
    float4 a = ((const float4*)p0)[idx];
    float4 b = ((const float4*)p1)[idx];
    float4 o;
    o.x = a.x + b.x + bv;
    o.y = a.y + b.y + bv;
    o.z = a.z + b.z + bv;
    o.w = a.w + b.w + bv;
    ((float4*)out)[idx] = o;
}

// ---------------------------------------------------------------------------
// Attention: 16x16 pixel tile per CTA; 256 threads = 128 x-adjacent pixel
// PAIRS x 2 roles (role 0: dy<=0, role 1: dy>0). Each K/V halo site is loaded
// ONCE and serves both pixels of the pair (halves LDS traffic).
// Halo 26x26 x 24 fp32 (K and V), pixel stride 28 floats -> conflict-free
// 16B-aligned LDS.128. 151 KB smem -> 1 CTA/SM; grid 128 CTAs.
// Static ring routing: for site at column offset dxA (rel. to pixel A),
// pixel A uses ring(max(|dy|,|dxA|)), pixel B uses ring(max(|dy|,|dxA-1|)).
// ---------------------------------------------------------------------------
#define PSTR 28
#define HCOLS 26
#define HPX (26 * 26)                    // 676
#define ATTN_SMEM (2 * HPX * PSTR * 4)   // 151424 B

__global__ __launch_bounds__(256, 1) void attn_kernel()
{
    extern __shared__ float sh[];
    float* Ksh = sh;
    float* Vsh = sh + HPX * PSTR;

    const int tile = blockIdx.x;     // 0..15
    const int head = blockIdx.y;
    const int b = blockIdx.z;
    const int th = (tile >> 2) << 4;
    const int tw = (tile & 3) << 4;
    const int h0 = th - 5, w0 = tw - 5;

    const float* base = g_qkv + (long)b * 288 * HW;
    const float* Kg = base + (96 + head * 24) * HW;
    const float* Vg = base + (192 + head * 24) * HW;

    const int tid = threadIdx.x;

    // ---- halo load: precompute <=3 sites per thread, then sweep d ----
    {
        int po[3]; int gi[3]; bool ok[3]; int cnt = 0;
        for (int p = tid; p < HPX; p += 256) {
            int py = p / HCOLS, px = p - py * HCOLS;
            int gy = h0 + py, gx = w0 + px;
            po[cnt] = p * PSTR;
            ok[cnt] = ((unsigned)gy < 64u) && ((unsigned)gx < 64u);
            gi[cnt] = ok[cnt] ? (gy * 64 + gx) : 0;
            cnt++;
        }
        for (int d = 0; d < 24; d++) {
            long doff = (long)d * HW;
            #pragma unroll
            for (int n = 0; n < 3; n++) {
                if (n < cnt) {
                    float kv = ok[n] ? Kg[doff + gi[n]] : 0.f;
                    float vv = ok[n] ? Vg[doff + gi[n]] : 0.f;
                    Ksh[po[n] + d] = kv;
                    Vsh[po[n] + d] = vv;
                }
            }
        }
    }
    __syncthreads();

    const int role = tid >> 7;            // 0: dy<=0, 1: dy>0
    const int pid = tid & 127;            // pair id
    const int py = pid >> 3;              // 0..15
    const int px0 = (pid & 7) * 2;        // 0,2,..,14  (pixel A; B = px0+1)

    // Q for both pixels, packed pairs, 1/sqrt(24) folded in
    const float* QgA = g_qkv + ((long)b * 288 + head * 24) * HW + (th + py) * 64 + (tw + px0);
    ull q2A[12], q2B[12];
    #pragma unroll
    for (int j = 0; j < 12; j++) {
        const float sc = 0.2041241452319315f;
        float a0 = QgA[(long)(2 * j) * HW]     * sc;
        float a1 = QgA[(long)(2 * j + 1) * HW] * sc;
        float b0 = QgA[(long)(2 * j) * HW + 1]     * sc;
        float b1 = QgA[(long)(2 * j + 1) * HW + 1] * sc;
        q2A[j] = pkpair(a0, a1);
        q2B[j] = pkpair(b0, b1);
    }

    ull aA7[12] = {}, aA9[12] = {}, aA11[12] = {};
    ull aB7[12] = {}, aB9[12] = {}, aB11[12] = {};
    float lA7 = 0.f, lA9 = 0.f, lA11 = 0.f;
    float lB7 = 0.f, lB9 = 0.f, lB11 = 0.f;
    const int cbase = (py + 5) * HCOLS + (px0 + 5);

#define SITE2(POFF, AA, LA, AB, LB) { \
    const ull* kp = (const ull*)(Ksh + (size_t)(cbase + (POFF)) * PSTR); \
    const ull* vp = (const ull*)(Vsh + (size_t)(cbase + (POFF)) * PSTR); \
    ull sa = 0ULL, sb = 0ULL, ta = 0ULL, tb = 0ULL; \
    _Pragma("unroll") for (int j = 0; j < 6; j++) { \
        ull k0_ = kp[j], k1_ = kp[j + 6]; \
        sa = ffma2(q2A[j], k0_, sa);  sb = ffma2(q2A[j + 6], k1_, sb); \
        ta = ffma2(q2B[j], k0_, ta);  tb = ffma2(q2B[j + 6], k1_, tb); } \
    float x0, x1, y0, y1; \
    upk(add2(sa, sb), x0, x1); upk(add2(ta, tb), y0, y1); \
    float eA = __expf(x0 + x1), eB = __expf(y0 + y1); \
    LA += eA; LB += eB; \
    ull pA = pk2(eA), pB = pk2(eB); \
    _Pragma("unroll") for (int j = 0; j < 12; j++) { \
        ull v = vp[j]; AA[j] = ffma2(pA, v, AA[j]); AB[j] = ffma2(pB, v, AB[j]); } \
}

#define SITE1(POFF, Q2, AC, L) { \
    const ull* kp = (const ull*)(Ksh + (size_t)(cbase + (POFF)) * PSTR); \
    const ull* vp = (const ull*)(Vsh + (size_t)(cbase + (POFF)) * PSTR); \
    ull sa = 0ULL, sb = 0ULL; \
    _Pragma("unroll") for (int j = 0; j < 6; j++) { \
        sa = ffma2(Q2[j], kp[j], sa); sb = ffma2(Q2[j + 6], kp[j + 6], sb); } \
    float x0, x1; upk(add2(sa, sb), x0, x1); \
    float e = __expf(x0 + x1); \
    L += e; ull pe = pk2(e); \
    _Pragma("unroll") for (int j = 0; j < 12; j++) AC[j] = ffma2(pe, vp[j], AC[j]); \
}

    // row with |dy| == 5: everything ring-11
#define ROW5(DY) { \
    SITE1((DY) * HCOLS - 5, q2A, aA11, lA11) \
    _Pragma("unroll 1") for (int dx = -4; dx <= 5; dx++) { SITE2((DY) * HCOLS + dx, aA11, lA11, aB11, lB11) } \
    SITE1((DY) * HCOLS + 6, q2B, aB11, lB11) \
}
    // row with |dy| == 4
#define ROW4(DY) { \
    SITE1((DY) * HCOLS - 5, q2A, aA11, lA11) \
    SITE2((DY) * HCOLS - 4, aA9, lA9, aB11, lB11) \
    _Pragma("unroll 1") for (int dx = -3; dx <= 4; dx++) { SITE2((DY) * HCOLS + dx, aA9, lA9, aB9, lB9) } \
    SITE2((DY) * HCOLS + 5, aA11, lA11, aB9, lB9) \
    SITE1((DY) * HCOLS + 6, q2B, aB11, lB11) \
}
    // row with |dy| <= 3
#define ROW3(DY) { \
    SITE1((DY) * HCOLS - 5, q2A, aA11, lA11) \
    SITE2((DY) * HCOLS - 4, aA9, lA9, aB11, lB11) \
    SITE2((DY) * HCOLS - 3, aA7, lA7, aB9, lB9) \
    _Pragma("unroll 1") for (int dx = -2; dx <= 3; dx++) { SITE2((DY) * HCOLS + dx, aA7, lA7, aB7, lB7) } \
    SITE2((DY) * HCOLS + 4, aA9, lA9, aB7, lB7) \
    SITE2((DY) * HCOLS + 5, aA11, lA11, aB9, lB9) \
    SITE1((DY) * HCOLS + 6, q2B, aB11, lB11) \
}

    if (role == 0) {
        ROW5(-5)
        ROW4(-4)
        #pragma unroll 1
        for (int dy = -3; dy <= 0; dy++) { ROW3(dy) }
    } else {
        #pragma unroll 1
        for (int dy = 1; dy <= 3; dy++) { ROW3(dy) }
        ROW4(4)
        ROW5(5)
    }
#undef SITE2
#undef SITE1
#undef ROW5
#undef ROW4
#undef ROW3

    // ---- combine roles through smem (aliases halo; safe after sync) ----
    __syncthreads();
    ull* red = (ull*)sh;            // 128 pairs * 75 ull = 76.8 KB
    if (role == 1) {
        ull* r = red + (size_t)pid * 75;
        #pragma unroll
        for (int j = 0; j < 12; j++) {
            r[j]      = aA7[j];  r[12 + j] = aA9[j];  r[24 + j] = aA11[j];
            r[36 + j] = aB7[j];  r[48 + j] = aB9[j];  r[60 + j] = aB11[j];
        }
        r[72] = pkpair(lA7, lA9);
        r[73] = pkpair(lA11, lB7);
        r[74] = pkpair(lB9, lB11);
    }
    __syncthreads();

    if (role == 0) {
        const ull* r = red + (size_t)pid * 75;
        #pragma unroll
        for (int j = 0; j < 12; j++) {
            aA7[j]  = add2(aA7[j],  r[j]);
            aA9[j]  = add2(aA9[j],  r[12 + j]);
            aA11[j] = add2(aA11[j], r[24 + j]);
            aB7[j]  = add2(aB7[j],  r[36 + j]);
            aB9[j]  = add2(aB9[j],  r[48 + j]);
            aB11[j] = add2(aB11[j], r[60 + j]);
        }
        float t0, t1;
        upk(r[72], t0, t1); lA7 += t0; lA9 += t1;
        upk(r[73], t0, t1); lA11 += t0; lB7 += t1;
        upk(r[74], t0, t1); lB9 += t0; lB11 += t1;

        float* A = g_att + ((long)b * 288 + head * 72) * HW + (th + py) * 64 + (tw + px0);

        // pixel A
        {
            const float r7  = __fdividef(1.f, lA7);
            const float t9  = lA7 + lA9;
            const float r9  = __fdividef(1.f, t9);
            const float r11 = __fdividef(1.f, t9 + lA11);
            #pragma unroll
            for (int j = 0; j < 12; j++) {
                float p70, p71, p90, p91, pb0, pb1;
                upk(aA7[j], p70, p71);
                upk(aA9[j], p90, p91);
                upk(aA11[j], pb0, pb1);
                float s90 = p70 + p90, s91 = p71 + p91;
                float sb0 = s90 + pb0, sb1 = s91 + pb1;
                A[(long)(2 * j) * HW]            = p70 * r7;
                A[(long)(2 * j + 1) * HW]        = p71 * r7;
                A[(long)(24 + 2 * j) * HW]       = s90 * r9;
                A[(long)(24 + 2 * j + 1) * HW]   = s91 * r9;
                A[(long)(48 + 2 * j) * HW]       = sb0 * r11;
                A[(long)(48 + 2 * j + 1) * HW]   = sb1 * r11;
            }
        }
        // pixel B
        {
            const float r7  = __fdividef(1.f, lB7);
            const float t9  = lB7 + lB9;
            const float r9  = __fdividef(1.f, t9);
            const float r11 = __fdividef(1.f, t9 + lB11);
            #pragma unroll
            for (int j = 0; j < 12; j++) {
                float p70, p71, p90, p91, pb0, pb1;
                upk(aB7[j], p70, p71);
                upk(aB9[j], p90, p91);
                upk(aB11[j], pb0, pb1);
                float s90 = p70 + p90, s91 = p71 + p91;
                float sb0 = s90 + pb0, sb1 = s91 + pb1;
                A[(long)(2 * j) * HW + 1]          = p70 * r7;
                A[(long)(2 * j + 1) * HW + 1]      = p71 * r7;
                A[(long)(24 + 2 * j) * HW + 1]     = s90 * r9;
                A[(long)(24 + 2 * j + 1) * HW + 1] = s91 * r9;
                A[(long)(48 + 2 * j) * HW + 1]     = sb0 * r11;
                A[(long)(48 + 2 * j + 1) * HW + 1] = sb1 * r11;
            }
        }
    }
}

// ---------------------------------------------------------------------------
extern "C" void kernel_launch(void* const* d_in, const int* in_sizes, int n_in,
                              void* d_out, int out_size)
{
    const float* x  = (const float*)d_in[0];
    const float* wq = (const float*)d_in[1];
    const float* bq = (const float*)d_in[2];
    const float* wk = (const float*)d_in[3];
    const float* bk = (const float*)d_in[4];
    const float* wv = (const float*)d_in[5];
    const float* bv = (const float*)d_in[6];
    const float* wo = (const float*)d_in[7];
    const float* bo = (const float*)d_in[8];
    float* out = (float*)d_out;

    float* qkv = nullptr;
    float* att = nullptr;
    cudaGetSymbolAddress((void**)&qkv, g_qkv);
    cudaGetSymbolAddress((void**)&att, g_att);

    cudaFuncSetAttribute(attn_kernel, cudaFuncAttributeMaxDynamicSharedMemorySize, ATTN_SMEM);

    // QKV projections (fused): grid (4096/64, 2, 3) = 384 CTAs
    gemm_k<96, 96, false><<<dim3(64, BATCH, 3), 128>>>(
        x, 96L * HW, 288L * HW,
        wq, wk, wv, bq, bk, bv,
        qkv, qkv + 96L * HW, qkv + 192L * HW);

    // Multi-range local attention: 128 CTAs, 1/SM (151 KB smem)
    attn_kernel<<<dim3(16, 4, BATCH), 256, ATTN_SMEM>>>();

    // Output projection, K split in 2 chunks of 144 -> partial slabs in g_qkv
    float* p0 = qkv;                       // [2][96][4096]
    float* p1 = qkv + (long)BATCH * 96 * HW;
    gemm_k<288, 144, true><<<dim3(64, BATCH, 2), 128>>>(
        att, 288L * HW, 96L * HW,
        wo, wo, wo, bo, bo, bo,
        p0, p1, p1);

    // out = p0 + p1 + bias
    finish_out<<<768, 256>>>(p0, p1, bo, out);
}